// round 7
// baseline (speedup 1.0000x reference)
#include <cuda_runtime.h>
#include <cstdint>

// ---------------------------------------------------------------------------
// Quan_adder2d: fake-quant(x, 16b global) ; fake-quant(W, 8b per-out-channel)
// out[n,f,ho,wo] = -sum_{c,i,j} | qw[f,c,i,j] - qx[n,c,ho+i-1,wo+j-1] |
// Integer formulation on the global 16-bit x grid:
//   sum|.| = s * sum |w_int - x_int|   (exact u16 SAD)
// vabsdiff2.u32.u32.u32.add: 2 channels per instruction, fused accumulate.
// ---------------------------------------------------------------------------

#define N_BATCH 4
#define C_IN    64
#define HW      28
#define F_OUT   64
#define KDIM    576
#define QX_MAX  65535.0f
#define QW_MAX  255.0f

#define MMB     32
#define SLICES  8
#define CPP     4             // channel-pairs per slice (8*4 = 32 pairs)
#define TPS     112
#define THREADS (SLICES*TPS)  // 896

__device__ float g_bmin[MMB];
__device__ float g_bmax[MMB];
__device__ float g_qw[KDIM * F_OUT];   // layout [k][f], dequantized floats

// SAD on packed u16x2 with accumulate: r = c + |alo-blo| + |ahi-bhi|
__device__ __forceinline__ unsigned sad2(unsigned a, unsigned b, unsigned c) {
    unsigned r;
    asm("vabsdiff2.u32.u32.u32.add %0, %1, %2, %3;"
        : "=r"(r) : "r"(a), "r"(b), "r"(c));
    return r;
}

// ---------------------------------------------------------------------------
// k_prep: blocks 0,1 -> W quant (coalesced transpose write to g_qw[k][f])
//         blocks 2..33 -> x min/max partials
// ---------------------------------------------------------------------------
#define PREP_SMEM (32 * 577 * 4)

__global__ void __launch_bounds__(1024, 1) k_prep(const float* __restrict__ W,
                                                  const float4* __restrict__ x,
                                                  int n4) {
    extern __shared__ float sq[];   // [32][577]
    const int tid = threadIdx.x;

    if (blockIdx.x >= 2) {
        int bid    = blockIdx.x - 2;
        int idx    = bid * 1024 + tid;
        int stride = MMB * 1024;
        float mn = 1e30f, mx = -1e30f;
        for (int i = idx; i < n4; i += stride) {
            float4 v = x[i];
            mn = fminf(fminf(fminf(mn, v.x), v.y), fminf(v.z, v.w));
            mx = fmaxf(fmaxf(fmaxf(mx, v.x), v.y), fmaxf(v.z, v.w));
        }
        #pragma unroll
        for (int o = 16; o > 0; o >>= 1) {
            mn = fminf(mn, __shfl_xor_sync(0xffffffffu, mn, o));
            mx = fmaxf(mx, __shfl_xor_sync(0xffffffffu, mx, o));
        }
        __shared__ float smn[32], smx[32];
        int warp = tid >> 5, lane = tid & 31;
        if (lane == 0) { smn[warp] = mn; smx[warp] = mx; }
        __syncthreads();
        if (warp == 0) {
            mn = smn[lane];
            mx = smx[lane];
            #pragma unroll
            for (int o = 16; o > 0; o >>= 1) {
                mn = fminf(mn, __shfl_xor_sync(0xffffffffu, mn, o));
                mx = fmaxf(mx, __shfl_xor_sync(0xffffffffu, mx, o));
            }
            if (lane == 0) { g_bmin[bid] = mn; g_bmax[bid] = mx; }
        }
        return;
    }

    const int warp = tid >> 5;
    const int lane = tid & 31;
    const int f    = blockIdx.x * 32 + warp;

    const float* wf = W + f * KDIM;
    float v[18];
    float mn = 1e30f, mx = -1e30f;
    #pragma unroll
    for (int t = 0; t < 18; ++t) {
        v[t] = wf[lane + t * 32];
        mn = fminf(mn, v[t]);
        mx = fmaxf(mx, v[t]);
    }
    #pragma unroll
    for (int o = 16; o > 0; o >>= 1) {
        mn = fminf(mn, __shfl_xor_sync(0xffffffffu, mn, o));
        mx = fmaxf(mx, __shfl_xor_sync(0xffffffffu, mx, o));
    }
    float scale = fmaxf(__fdiv_rn(mx - mn, QW_MAX), 1e-12f);
    float zp    = rintf(__fdiv_rn(-mn, scale));
    #pragma unroll
    for (int t = 0; t < 18; ++t) {
        float q = fminf(fmaxf(rintf(__fdiv_rn(v[t], scale)) + zp, 0.0f), QW_MAX);
        sq[warp * 577 + lane + t * 32] = (q - zp) * scale;
    }
    __syncthreads();

    const int j  = tid & 31;
    const int kk = tid >> 5;
    const int f0 = blockIdx.x * 32;
    #pragma unroll
    for (int p = 0; p < 18; ++p) {
        int k = p * 32 + kk;
        g_qw[k * F_OUT + f0 + j] = sq[j * 577 + k];
    }
}

// ---------------------------------------------------------------------------
// k_main: integer SAD adder-conv. grid (28 ho, 4 n), 896 threads = 8 x 112
// ---------------------------------------------------------------------------
#define SWI_OFF   0                    // [288][64] u16x2 w pairs
#define SXI_OFF   18432                // [32][3][32] u16x2 x pairs
#define RED_OFF   21504                // 1792 uint4 = 7168 u32
#define SPRM_OFF  28672
#define SMEM_U32  28674
#define SMEM_BYTES (SMEM_U32 * 4)      // 114696

__global__ void __launch_bounds__(THREADS, 1) k_main(const float* __restrict__ x,
                                                     float* __restrict__ out) {
    const int ho  = blockIdx.x;
    const int n   = blockIdx.y;
    const int tid = threadIdx.x;

    extern __shared__ unsigned smem[];
    unsigned* swi  = smem + SWI_OFF;
    unsigned* sxi  = smem + SXI_OFF;
    uint4*    red  = (uint4*)(smem + RED_OFF);
    float*    sprm = (float*)(smem + SPRM_OFF);

    // warp 0: finalize activation quant params from 32 partials
    if (tid < 32) {
        float mn = g_bmin[tid];
        float mx = g_bmax[tid];
        #pragma unroll
        for (int o = 16; o > 0; o >>= 1) {
            mn = fminf(mn, __shfl_xor_sync(0xffffffffu, mn, o));
            mx = fmaxf(mx, __shfl_xor_sync(0xffffffffu, mx, o));
        }
        if (tid == 0) {
            float scale = fmaxf(__fdiv_rn(mx - mn, QX_MAX), 1e-12f);
            sprm[0] = scale;
            sprm[1] = rintf(__fdiv_rn(-mn, scale));
        }
    }
    __syncthreads();

    const float s    = sprm[0];
    const float zp   = sprm[1];
    const float invs = __fdiv_rn(1.0f, s);

    // stage W: re-grid dequantized qw onto the global x grid, pack (c, c+32)
    for (int idx = tid; idx < 18432; idx += THREADS) {
        float wlo = g_qw[idx];               // k = idx>>6, f = idx&63
        float whi = g_qw[idx + 288 * 64];    // channel c+32, same (i,j,f)
        float qlo = fminf(fmaxf(rintf(wlo * invs) + zp, 0.0f), 65535.0f);
        float qhi = fminf(fmaxf(rintf(whi * invs) + zp, 0.0f), 65535.0f);
        swi[idx] = (unsigned)qlo | ((unsigned)qhi << 16);
    }

    // stage x: quantize to grid indices, pack (c, c+32); padding -> zp index
    const unsigned zpu = (unsigned)zp;
    for (int idx = tid; idx < 2880; idx += THREADS) {
        int c   = idx / 90;
        int rem = idx - c * 90;
        int i   = rem / 30;
        int col = rem - i * 30;
        int h   = ho + i - 1;
        int w   = col - 1;
        unsigned vlo = zpu, vhi = zpu;
        if ((unsigned)h < (unsigned)HW && (unsigned)w < (unsigned)HW) {
            float a = x[((n * C_IN + c) * HW + h) * HW + w];
            float b = x[((n * C_IN + c + 32) * HW + h) * HW + w];
            vlo = (unsigned)fminf(fmaxf(rintf(__fdiv_rn(a, s)) + zp, 0.0f), QX_MAX);
            vhi = (unsigned)fminf(fmaxf(rintf(__fdiv_rn(b, s)) + zp, 0.0f), QX_MAX);
        }
        sxi[c * 96 + i * 32 + col] = vlo | (vhi << 16);
    }
    for (int idx = tid; idx < 192; idx += THREADS) {
        int c = idx / 6;
        int rem = idx - c * 6;
        int i = rem >> 1;
        int col = 30 + (rem & 1);
        sxi[c * 96 + i * 32 + col] = 0;
    }
    __syncthreads();

    // ---- main loop: pure SAD ----
    const int slice = tid / TPS;          // 0..7
    const int t     = tid - slice * TPS;  // 0..111
    const int fgrp  = t & 15;
    const int wog   = t >> 4;             // 0..6
    const int f0    = fgrp * 4;
    const int wo0   = wog * 4;
    const int cp0   = slice * CPP;

    unsigned acc[4][4];
    #pragma unroll
    for (int a = 0; a < 4; ++a)
        #pragma unroll
        for (int b = 0; b < 4; ++b) acc[a][b] = 0u;

    const unsigned* xrow = sxi + cp0 * 96;
    const unsigned* wrow = swi + cp0 * 9 * 64 + f0;

    #pragma unroll
    for (int cp = 0; cp < CPP; ++cp) {
        #pragma unroll
        for (int i = 0; i < 3; ++i) {
            uint4 wp0 = *(const uint4*)(wrow + (i * 3 + 0) * 64);
            uint4 wp1 = *(const uint4*)(wrow + (i * 3 + 1) * 64);
            uint4 wp2 = *(const uint4*)(wrow + (i * 3 + 2) * 64);
            const unsigned* xr = xrow + i * 32 + wo0;
            uint4 xa = *(const uint4*)xr;
            uint2 xb = *(const uint2*)(xr + 4);
            unsigned xs[6] = { xa.x, xa.y, xa.z, xa.w, xb.x, xb.y };
            #pragma unroll
            for (int k = 0; k < 4; ++k) {
                unsigned x0 = xs[k], x1 = xs[k + 1], x2 = xs[k + 2];
                acc[0][k] = sad2(wp0.x, x0, acc[0][k]);
                acc[1][k] = sad2(wp0.y, x0, acc[1][k]);
                acc[2][k] = sad2(wp0.z, x0, acc[2][k]);
                acc[3][k] = sad2(wp0.w, x0, acc[3][k]);
                acc[0][k] = sad2(wp1.x, x1, acc[0][k]);
                acc[1][k] = sad2(wp1.y, x1, acc[1][k]);
                acc[2][k] = sad2(wp1.z, x1, acc[2][k]);
                acc[3][k] = sad2(wp1.w, x1, acc[3][k]);
                acc[0][k] = sad2(wp2.x, x2, acc[0][k]);
                acc[1][k] = sad2(wp2.y, x2, acc[1][k]);
                acc[2][k] = sad2(wp2.z, x2, acc[2][k]);
                acc[3][k] = sad2(wp2.w, x2, acc[3][k]);
            }
        }
        xrow += 96;
        wrow += 9 * 64;
    }

    uint4 va[4];
    #pragma unroll
    for (int fl = 0; fl < 4; ++fl)
        va[fl] = make_uint4(acc[fl][0], acc[fl][1], acc[fl][2], acc[fl][3]);

#define RSLOT(sl, fl) red[(((sl) * TPS + t) << 2) + (fl)]
#define RADD(sl)                                                  \
    { _Pragma("unroll") for (int fl = 0; fl < 4; ++fl) {          \
        uint4 o = RSLOT(sl, fl);                                  \
        va[fl].x += o.x; va[fl].y += o.y;                         \
        va[fl].z += o.z; va[fl].w += o.w; } }
#define RSTORE(sl)                                                \
    { _Pragma("unroll") for (int fl = 0; fl < 4; ++fl) RSLOT(sl, fl) = va[fl]; }

    // 8 -> 4 -> 2 -> 1
    if (slice >= 4) RSTORE(slice - 4);
    __syncthreads();
    if (slice < 4) RADD(slice);
    __syncthreads();
    if (slice == 2 || slice == 3) RSTORE(slice - 2);
    __syncthreads();
    if (slice < 2) RADD(slice);
    __syncthreads();
    if (slice == 1) RSTORE(0);
    __syncthreads();
    if (slice == 0) {
        RADD(0);
        float* op = out + ((n * F_OUT + f0) * HW + ho) * HW + wo0;
        const float ns = -s;
        #pragma unroll
        for (int fl = 0; fl < 4; ++fl) {
            float4 o;
            o.x = ns * (float)(int)va[fl].x;
            o.y = ns * (float)(int)va[fl].y;
            o.z = ns * (float)(int)va[fl].z;
            o.w = ns * (float)(int)va[fl].w;
            *(float4*)(op + fl * HW * HW) = o;
        }
    }
#undef RSLOT
#undef RADD
#undef RSTORE
}

extern "C" void kernel_launch(void* const* d_in, const int* in_sizes, int n_in,
                              void* d_out, int out_size) {
    const float* x = (const float*)d_in[0];
    const float* W = (const float*)d_in[1];
    float* out = (float*)d_out;

    cudaFuncSetAttribute(k_prep, cudaFuncAttributeMaxDynamicSharedMemorySize,
                         PREP_SMEM);
    cudaFuncSetAttribute(k_main, cudaFuncAttributeMaxDynamicSharedMemorySize,
                         SMEM_BYTES);

    k_prep<<<MMB + 2, 1024, PREP_SMEM>>>(W, (const float4*)x,
                                         (N_BATCH * C_IN * HW * HW) / 4);
    dim3 grid(HW, N_BATCH);
    k_main<<<grid, THREADS, SMEM_BYTES>>>(x, out);
}

// round 8
// speedup vs baseline: 2.2444x; 2.2444x over previous
#include <cuda_runtime.h>
#include <cstdint>

// ---------------------------------------------------------------------------
// Quan_adder2d: fake-quant(x, 16b global) ; fake-quant(W, 8b per-out-channel)
// out[n,f,ho,wo] = -sum_{c,i,j} | qw[f,c,i,j] - qx[n,c,ho+i-1,wo+j-1] |
// Integer min-trick on the global 16-bit x grid:
//   sum|.| = s * (W_SUM[f] + X_SUM[win] - 2*sum min(w_int, x_int))
// min.u16x2 (2 channels packed) + dp2a accumulate.
// k_prep produces packed ints + W sums; k_main runs 2 blocks/SM (f-split).
// ---------------------------------------------------------------------------

#define N_BATCH 4
#define C_IN    64
#define HW      28
#define F_OUT   64
#define KDIM    576
#define QX_MAX  65535.0f
#define QW_MAX  255.0f

#define MMB     32
#define SLICES  8
#define CPP     4             // channel-pairs per slice (8*4 = 32 pairs)
#define TPS     56            // 8 fgrp x 7 wog
#define THREADS (SLICES*TPS)  // 448

__device__ float    g_bmin[MMB];
__device__ float    g_bmax[MMB];
__device__ unsigned g_cnt = 0;            // minmax completion counter
__device__ float    g_sprm[2];            // xscale, xzp
__device__ unsigned g_wsum[F_OUT];        // per-f integer weight sums
__device__ unsigned g_swi[2 * 288 * 32];  // [fhalf][k'=288][f'=32] packed u16x2

__device__ __forceinline__ unsigned minu2(unsigned a, unsigned b) {
    unsigned r;
    asm("min.u16x2 %0, %1, %2;" : "=r"(r) : "r"(a), "r"(b));
    return r;
}
#define DPB 0x00000101u   // dp2a byte pair (1,1): sums both u16 halves

// ---------------------------------------------------------------------------
// k_prep: blocks 0,1 -> W quant + regrid + pack (spin-wait for x minmax)
//         blocks 2..33 -> x min/max partials, fence, count
// ---------------------------------------------------------------------------
#define PREP_SMEM (32 * 289 * 4)   // 36992 B

__global__ void __launch_bounds__(1024, 1) k_prep(const float* __restrict__ W,
                                                  const float4* __restrict__ x,
                                                  int n4) {
    extern __shared__ unsigned sp[];   // W blocks: [32 f][289] packed
    const int tid = threadIdx.x;

    if (blockIdx.x >= 2) {
        // ---- x global min/max partial ----
        int bid    = blockIdx.x - 2;
        int idx    = bid * 1024 + tid;
        int stride = MMB * 1024;
        float mn = 1e30f, mx = -1e30f;
        for (int i = idx; i < n4; i += stride) {
            float4 v = x[i];
            mn = fminf(fminf(fminf(mn, v.x), v.y), fminf(v.z, v.w));
            mx = fmaxf(fmaxf(fmaxf(mx, v.x), v.y), fmaxf(v.z, v.w));
        }
        #pragma unroll
        for (int o = 16; o > 0; o >>= 1) {
            mn = fminf(mn, __shfl_xor_sync(0xffffffffu, mn, o));
            mx = fmaxf(mx, __shfl_xor_sync(0xffffffffu, mx, o));
        }
        __shared__ float smn[32], smx[32];
        int warp = tid >> 5, lane = tid & 31;
        if (lane == 0) { smn[warp] = mn; smx[warp] = mx; }
        __syncthreads();
        if (warp == 0) {
            mn = smn[lane];
            mx = smx[lane];
            #pragma unroll
            for (int o = 16; o > 0; o >>= 1) {
                mn = fminf(mn, __shfl_xor_sync(0xffffffffu, mn, o));
                mx = fmaxf(mx, __shfl_xor_sync(0xffffffffu, mx, o));
            }
            if (lane == 0) {
                g_bmin[bid] = mn;
                g_bmax[bid] = mx;
                __threadfence();
                atomicAdd(&g_cnt, 1u);
            }
        }
        return;
    }

    // ---- W path: block b handles f = b*32 .. b*32+31, warp = local f ----
    const int b    = blockIdx.x;
    const int warp = tid >> 5;
    const int lane = tid & 31;
    const int f    = b * 32 + warp;

    const float* wf = W + f * KDIM;
    float v[18];
    float mn = 1e30f, mx = -1e30f;
    #pragma unroll
    for (int t = 0; t < 18; ++t) {       // k = lane + t*32
        v[t] = wf[lane + t * 32];
        mn = fminf(mn, v[t]);
        mx = fmaxf(mx, v[t]);
    }
    #pragma unroll
    for (int o = 16; o > 0; o >>= 1) {
        mn = fminf(mn, __shfl_xor_sync(0xffffffffu, mn, o));
        mx = fmaxf(mx, __shfl_xor_sync(0xffffffffu, mx, o));
    }
    float scale = fmaxf(__fdiv_rn(mx - mn, QW_MAX), 1e-12f);
    float zp    = rintf(__fdiv_rn(-mn, scale));
    #pragma unroll
    for (int t = 0; t < 18; ++t) {       // dequantized weight (float)
        float q = fminf(fmaxf(rintf(__fdiv_rn(v[t], scale)) + zp, 0.0f), QW_MAX);
        v[t] = (q - zp) * scale;
    }

    // wait for x min/max; finalize activation quant params
    __shared__ float xs_s[2];
    if (tid == 0) {
        while (*(volatile unsigned*)&g_cnt < (unsigned)MMB) __nanosleep(64);
        __threadfence();
        float xmn = 1e30f, xmx = -1e30f;
        #pragma unroll
        for (int i = 0; i < MMB; ++i) {
            xmn = fminf(xmn, g_bmin[i]);
            xmx = fmaxf(xmx, g_bmax[i]);
        }
        float xs = fmaxf(__fdiv_rn(xmx - xmn, QX_MAX), 1e-12f);
        xs_s[0] = xs;
        xs_s[1] = rintf(__fdiv_rn(-xmn, xs));
        if (b == 0) { g_sprm[0] = xs_s[0]; g_sprm[1] = xs_s[1]; }
    }
    __syncthreads();
    const float xs   = xs_s[0];
    const float xzp  = xs_s[1];
    const float invs = __fdiv_rn(1.0f, xs);

    // re-grid onto x grid, pack channel pairs (k', k'+288) = (c, c+32)
    unsigned wq[18];
    #pragma unroll
    for (int t = 0; t < 18; ++t)
        wq[t] = (unsigned)fminf(fmaxf(rintf(v[t] * invs) + xzp, 0.0f), 65535.0f);
    unsigned ssum = 0;
    #pragma unroll
    for (int t = 0; t < 9; ++t) {        // pair: k'=lane+t*32 with k'+288
        unsigned p = wq[t] | (wq[t + 9] << 16);
        sp[warp * 289 + lane + t * 32] = p;
        ssum = __dp2a_lo(p, DPB, ssum);
    }
    #pragma unroll
    for (int o = 16; o > 0; o >>= 1)
        ssum += __shfl_xor_sync(0xffffffffu, ssum, o);
    if (lane == 0) g_wsum[f] = ssum;
    __syncthreads();

    // transposed coalesced store: g_swi[b][k'][f']
    const int j  = tid & 31;   // f'
    const int kk = tid >> 5;
    #pragma unroll
    for (int p = 0; p < 9; ++p) {
        int k2 = p * 32 + kk;
        g_swi[b * 9216 + k2 * 32 + j] = sp[j * 289 + k2];
    }
}

// ---------------------------------------------------------------------------
// k_main: grid (28 ho, 4 n, 2 fhalf), 448 threads, 2 blocks/SM
// ---------------------------------------------------------------------------
#define SWI_OFF   0                    // [288][32] packed w
#define SXI_OFF   9216                 // [32 cp][3][32] packed x
#define RED_OFF   12288                // 896 uint4 = 3584 u32
#define RPART_OFF 15872                // [30][8]
#define RS_OFF    16112                // [30]
#define SMEM_U32  16142
#define SMEM_BYTES (SMEM_U32 * 4)      // 64568

__global__ void __launch_bounds__(THREADS, 2) k_main(const float* __restrict__ x,
                                                     float* __restrict__ out) {
    const int ho  = blockIdx.x;
    const int n   = blockIdx.y;
    const int fh  = blockIdx.z;
    const int tid = threadIdx.x;

    // reset the prep counter for the next launch (stream-ordered, one thread)
    if (tid == 0 && ho == 0 && n == 0 && fh == 0) g_cnt = 0u;

    extern __shared__ unsigned smem[];
    unsigned* swi   = smem + SWI_OFF;
    unsigned* sxi   = smem + SXI_OFF;
    uint4*    red   = (uint4*)(smem + RED_OFF);
    unsigned* rpart = smem + RPART_OFF;
    unsigned* rs    = smem + RS_OFF;

    const float s   = g_sprm[0];
    const float zp  = g_sprm[1];

    // stage this block's packed W half (straight copy, 36KB)
    {
        const uint4* gsrc = (const uint4*)(g_swi + fh * 9216);
        uint4*       sdst = (uint4*)swi;
        for (int i = tid; i < 2304; i += THREADS) sdst[i] = gsrc[i];
    }

    // stage x: quantize to grid indices, pack (c, c+32); padding -> zp index
    const unsigned zpu = (unsigned)zp;
    for (int idx = tid; idx < 2880; idx += THREADS) {
        int c   = idx / 90;
        int rem = idx - c * 90;
        int i   = rem / 30;
        int col = rem - i * 30;
        int h   = ho + i - 1;
        int w   = col - 1;
        unsigned vlo = zpu, vhi = zpu;
        if ((unsigned)h < (unsigned)HW && (unsigned)w < (unsigned)HW) {
            float a = x[((n * C_IN + c) * HW + h) * HW + w];
            float bb = x[((n * C_IN + c + 32) * HW + h) * HW + w];
            vlo = (unsigned)fminf(fmaxf(rintf(__fdiv_rn(a, s)) + zp, 0.0f), QX_MAX);
            vhi = (unsigned)fminf(fmaxf(rintf(__fdiv_rn(bb, s)) + zp, 0.0f), QX_MAX);
        }
        sxi[c * 96 + i * 32 + col] = vlo | (vhi << 16);
    }
    __syncthreads();

    // x window column-sum partials (for X_SUM correction)
    if (tid < 240) {   // col = tid/8, p = tid&7
        int col = tid >> 3;
        int p   = tid & 7;
        unsigned ssum = 0;
        #pragma unroll
        for (int cc = 0; cc < 4; ++cc)
            #pragma unroll
            for (int i = 0; i < 3; ++i)
                ssum = __dp2a_lo(sxi[(p * 4 + cc) * 96 + i * 32 + col], DPB, ssum);
        rpart[col * 8 + p] = ssum;
    }

    // ---- main loop ----
    const int slice = tid / TPS;          // 0..7
    const int t     = tid - slice * TPS;  // 0..55
    const int fgrp  = t & 7;              // f0 = 4*fgrp (0..28)
    const int wog   = t >> 3;             // 0..6
    const int f0    = fgrp * 4;
    const int wo0   = wog * 4;
    const int cp0   = slice * CPP;

    unsigned acc[4][4];
    #pragma unroll
    for (int a = 0; a < 4; ++a)
        #pragma unroll
        for (int b2 = 0; b2 < 4; ++b2) acc[a][b2] = 0u;

    const unsigned* xrow = sxi + cp0 * 96;
    const unsigned* wrow = swi + cp0 * 9 * 32 + f0;

    #pragma unroll
    for (int cp = 0; cp < CPP; ++cp) {
        #pragma unroll
        for (int i = 0; i < 3; ++i) {
            uint4 wp0 = *(const uint4*)(wrow + (i * 3 + 0) * 32);
            uint4 wp1 = *(const uint4*)(wrow + (i * 3 + 1) * 32);
            uint4 wp2 = *(const uint4*)(wrow + (i * 3 + 2) * 32);
            const unsigned* xr = xrow + i * 32 + wo0;
            uint4 xa = *(const uint4*)xr;
            uint2 xb = *(const uint2*)(xr + 4);
            unsigned xsv[6] = { xa.x, xa.y, xa.z, xa.w, xb.x, xb.y };
            #pragma unroll
            for (int k = 0; k < 4; ++k) {
                unsigned x0 = xsv[k], x1 = xsv[k + 1], x2 = xsv[k + 2];
                acc[0][k] = __dp2a_lo(minu2(wp0.x, x0), DPB, acc[0][k]);
                acc[1][k] = __dp2a_lo(minu2(wp0.y, x0), DPB, acc[1][k]);
                acc[2][k] = __dp2a_lo(minu2(wp0.z, x0), DPB, acc[2][k]);
                acc[3][k] = __dp2a_lo(minu2(wp0.w, x0), DPB, acc[3][k]);
                acc[0][k] = __dp2a_lo(minu2(wp1.x, x1), DPB, acc[0][k]);
                acc[1][k] = __dp2a_lo(minu2(wp1.y, x1), DPB, acc[1][k]);
                acc[2][k] = __dp2a_lo(minu2(wp1.z, x1), DPB, acc[2][k]);
                acc[3][k] = __dp2a_lo(minu2(wp1.w, x1), DPB, acc[3][k]);
                acc[0][k] = __dp2a_lo(minu2(wp2.x, x2), DPB, acc[0][k]);
                acc[1][k] = __dp2a_lo(minu2(wp2.y, x2), DPB, acc[1][k]);
                acc[2][k] = __dp2a_lo(minu2(wp2.z, x2), DPB, acc[2][k]);
                acc[3][k] = __dp2a_lo(minu2(wp2.w, x2), DPB, acc[3][k]);
            }
        }
        xrow += 96;
        wrow += 9 * 32;
    }

    uint4 va[4];
    #pragma unroll
    for (int fl = 0; fl < 4; ++fl)
        va[fl] = make_uint4(acc[fl][0], acc[fl][1], acc[fl][2], acc[fl][3]);

#define RSLOT(sl, fl) red[(((sl) * TPS + t) << 2) + (fl)]
#define RADD(sl)                                                  \
    { _Pragma("unroll") for (int fl = 0; fl < 4; ++fl) {          \
        uint4 o = RSLOT(sl, fl);                                  \
        va[fl].x += o.x; va[fl].y += o.y;                         \
        va[fl].z += o.z; va[fl].w += o.w; } }
#define RSTORE(sl)                                                \
    { _Pragma("unroll") for (int fl = 0; fl < 4; ++fl) RSLOT(sl, fl) = va[fl]; }

    // 8 -> 4 -> 2 -> 1 (rs finalized in parallel)
    if (slice >= 4) RSTORE(slice - 4);
    if (tid < 30) {
        unsigned ssum = 0;
        #pragma unroll
        for (int p = 0; p < 8; ++p) ssum += rpart[tid * 8 + p];
        rs[tid] = ssum;
    }
    __syncthreads();
    if (slice < 4) RADD(slice);
    __syncthreads();
    if (slice == 2 || slice == 3) RSTORE(slice - 2);
    __syncthreads();
    if (slice < 2) RADD(slice);
    __syncthreads();
    if (slice == 1) RSTORE(0);
    __syncthreads();
    if (slice == 0) {
        RADD(0);
        int xsum[4];
        #pragma unroll
        for (int k = 0; k < 4; ++k)
            xsum[k] = (int)(rs[wo0 + k] + rs[wo0 + k + 1] + rs[wo0 + k + 2]);
        const int fbase = fh * 32 + f0;
        float* op = out + ((n * F_OUT + fbase) * HW + ho) * HW + wo0;
        #pragma unroll
        for (int fl = 0; fl < 4; ++fl) {
            int ws = (int)g_wsum[fbase + fl];
            float4 o;
            o.x = s * (float)(2 * (int)va[fl].x - ws - xsum[0]);
            o.y = s * (float)(2 * (int)va[fl].y - ws - xsum[1]);
            o.z = s * (float)(2 * (int)va[fl].z - ws - xsum[2]);
            o.w = s * (float)(2 * (int)va[fl].w - ws - xsum[3]);
            *(float4*)(op + fl * HW * HW) = o;
        }
    }
#undef RSLOT
#undef RADD
#undef RSTORE
}

extern "C" void kernel_launch(void* const* d_in, const int* in_sizes, int n_in,
                              void* d_out, int out_size) {
    const float* x = (const float*)d_in[0];
    const float* W = (const float*)d_in[1];
    float* out = (float*)d_out;

    cudaFuncSetAttribute(k_prep, cudaFuncAttributeMaxDynamicSharedMemorySize,
                         PREP_SMEM);
    cudaFuncSetAttribute(k_main, cudaFuncAttributeMaxDynamicSharedMemorySize,
                         SMEM_BYTES);

    k_prep<<<MMB + 2, 1024, PREP_SMEM>>>(W, (const float4*)x,
                                         (N_BATCH * C_IN * HW * HW) / 4);
    dim3 grid(HW, N_BATCH, 2);
    k_main<<<grid, THREADS, SMEM_BYTES>>>(x, out);
}